// round 5
// baseline (speedup 1.0000x reference)
#include <cuda_runtime.h>

// f (32,512,512) f32, K (5,5,512,512) f32, dt (32,) -> out = relu(f + dt * conv_unshared5x5(f, K))
#define BATCH 32
#define H 512
#define W 512
#define HW (H * W)
#define HALO 2

// Output tile 32 x 8 per block, 128 threads (32 x, 4 y-groups), VY=2 pixels/thread.
// Batch as float4 (4 batches per LDS.128). GSTAGE=2 groups (8 batches) staged per
// sync, 4 stages. K taps are re-loaded per row per stage via __ldg (L1/L2-cached)
// instead of held in registers -> regs <= 64 -> 8 CTAs/SM, single wave.
#define TILE_X 32
#define TILE_Y 8
#define SM_ROWS 12              // TILE_Y + 2*HALO
#define SM_COLS 36              // TILE_X + 2*HALO
#define NPOS (SM_ROWS * SM_COLS)  // 432
#define GSTAGE 2
#define NSTAGE 4

#define FMA4(acc, fv, kk)                     \
    acc.x = fmaf(fv.x, kk, acc.x);            \
    acc.y = fmaf(fv.y, kk, acc.y);            \
    acc.z = fmaf(fv.z, kk, acc.z);            \
    acc.w = fmaf(fv.w, kk, acc.w);

__global__ __launch_bounds__(128, 8) void op2d_kernel(
    const float* __restrict__ f,
    const float* __restrict__ Kk,
    const float* __restrict__ dt,
    float* __restrict__ out)
{
    __shared__ float4 fs[GSTAGE][SM_ROWS][SM_COLS];  // 13824 B
    __shared__ __align__(16) float dts[BATCH];

    const int tid = threadIdx.x;
    const int tx = tid & 31;
    const int ty = tid >> 5;
    const int tileX = blockIdx.x * TILE_X;
    const int tileY = blockIdx.y * TILE_Y;

    if (tid < BATCH) dts[tid] = dt[tid];

    const int y0 = tileY + ty * 2;   // thread's top pixel row
    const int x  = tileX + tx;
    const int ry = ty * 2;

    const float* K0p = Kk + y0 * W + x;        // tap t for pixel0 at K0p[t*HW]
    const float* K1p = Kk + (y0 + 1) * W + x;  // tap t for pixel1 at K1p[t*HW]
    float* outp = out + y0 * W + x;

    #pragma unroll 1
    for (int s = 0; s < NSTAGE; s++) {
        __syncthreads();                 // previous stage's compute done

        // ---- Stage 8 batches: coalesced LDG, conflict-free STS.128 ----
        const int b0 = s * (GSTAGE * 4);
        #pragma unroll
        for (int it = 0; it < 4; it++) { // ceil(432/128) = 4 (last partial)
            const int p = tid + it * 128;
            if (p < NPOS) {
                const int r = p / SM_COLS;
                const int c = p - r * SM_COLS;
                const int gy = tileY + r - HALO;
                const int gx = tileX + c - HALO;
                const bool in = ((unsigned)gy < (unsigned)H) & ((unsigned)gx < (unsigned)W);
                const float* fp = f + (b0 * HW + gy * W + gx);
                #pragma unroll
                for (int g = 0; g < GSTAGE; g++) {
                    float4 v;
                    v.x = in ? fp[(g * 4 + 0) * HW] : 0.0f;
                    v.y = in ? fp[(g * 4 + 1) * HW] : 0.0f;
                    v.z = in ? fp[(g * 4 + 2) * HW] : 0.0f;
                    v.w = in ? fp[(g * 4 + 3) * HW] : 0.0f;
                    fs[g][r][c] = v;
                }
            }
        }
        __syncthreads();

        // ---- Compute: row-major over the 6-row footprint; K taps via __ldg ----
        float4 a00 = make_float4(0.f, 0.f, 0.f, 0.f);  // group0, pixel0
        float4 a01 = make_float4(0.f, 0.f, 0.f, 0.f);  // group0, pixel1
        float4 a10 = make_float4(0.f, 0.f, 0.f, 0.f);  // group1, pixel0
        float4 a11 = make_float4(0.f, 0.f, 0.f, 0.f);  // group1, pixel1

        #pragma unroll
        for (int r = 0; r < 6; r++) {
            float k0r[5], k1r[5];
            if (r < 5) {
                #pragma unroll
                for (int j = 0; j < 5; j++) k0r[j] = __ldg(&K0p[(r * 5 + j) * HW]);
            }
            if (r >= 1) {
                #pragma unroll
                for (int j = 0; j < 5; j++) k1r[j] = __ldg(&K1p[((r - 1) * 5 + j) * HW]);
            }
            #pragma unroll
            for (int j = 0; j < 5; j++) {
                float4 fv0 = fs[0][ry + r][tx + j];
                if (r < 5)  { FMA4(a00, fv0, k0r[j]); }
                if (r >= 1) { FMA4(a01, fv0, k1r[j]); }
                float4 fv1 = fs[1][ry + r][tx + j];
                if (r < 5)  { FMA4(a10, fv1, k0r[j]); }
                if (r >= 1) { FMA4(a11, fv1, k1r[j]); }
            }
        }

        // ---- Epilogue: out = relu(f + dt*acc) for 8 batches ----
        #pragma unroll
        for (int g = 0; g < GSTAGE; g++) {
            const int b = b0 + g * 4;
            const float4 dt4 = *(const float4*)&dts[b];
            const float4 fc0 = fs[g][ry + HALO][tx + HALO];
            const float4 fc1 = fs[g][ry + HALO + 1][tx + HALO];
            const float4 p0 = (g == 0) ? a00 : a10;
            const float4 p1 = (g == 0) ? a01 : a11;

            float* o = outp + b * HW;
            o[0] = fmaxf(fmaf(p0.x, dt4.x, fc0.x), 0.0f);
            o[W] = fmaxf(fmaf(p1.x, dt4.x, fc1.x), 0.0f);
            o += HW;
            o[0] = fmaxf(fmaf(p0.y, dt4.y, fc0.y), 0.0f);
            o[W] = fmaxf(fmaf(p1.y, dt4.y, fc1.y), 0.0f);
            o += HW;
            o[0] = fmaxf(fmaf(p0.z, dt4.z, fc0.z), 0.0f);
            o[W] = fmaxf(fmaf(p1.z, dt4.z, fc1.z), 0.0f);
            o += HW;
            o[0] = fmaxf(fmaf(p0.w, dt4.w, fc0.w), 0.0f);
            o[W] = fmaxf(fmaf(p1.w, dt4.w, fc1.w), 0.0f);
        }
    }
}

extern "C" void kernel_launch(void* const* d_in, const int* in_sizes, int n_in,
                              void* d_out, int out_size)
{
    const float* f  = (const float*)d_in[0];
    const float* Kk = (const float*)d_in[1];
    const float* dt = (const float*)d_in[2];
    float* out = (float*)d_out;

    dim3 grid(W / TILE_X, H / TILE_Y);  // (16, 64) = 1024 blocks -> 1 wave @ 8 CTAs/SM
    dim3 block(128);
    op2d_kernel<<<grid, block>>>(f, Kk, dt, out);
}